// round 12
// baseline (speedup 1.0000x reference)
#include <cuda_runtime.h>
#include <cuda_fp16.h>
#include <cstdint>

#define NB      32768
#define NH      16
#define HD      64
#define DMODEL  1024
#define RPC     4

typedef unsigned long long u64t;

// ---------------- scratch (device globals; no allocs allowed) ----------------
__device__ __half g_mixed[(size_t)2 * NB * DMODEL];   // [x_mixed ; v_mixed] fp16
__device__ __half g_woh[DMODEL * DMODEL];             // Wo fp16
__device__ __half g_wqh[HD * HD], g_wql[HD * HD];     // Wq split hi/lo fp16
__device__ __half g_wkh[HD * HD], g_wkl[HD * HD];     // Wk split hi/lo fp16

// ---------------- packed f32x2 helpers ----------------
__device__ __forceinline__ u64t pack2(float lo, float hi) {
    u64t r; asm("mov.b64 %0, {%1, %2};" : "=l"(r) : "f"(lo), "f"(hi)); return r;
}
__device__ __forceinline__ void unpack2(u64t v, float& lo, float& hi) {
    asm("mov.b64 {%0, %1}, %2;" : "=f"(lo), "=f"(hi) : "l"(v));
}
__device__ __forceinline__ u64t fma2(u64t a, u64t b, u64t c) {
    u64t d; asm("fma.rn.f32x2 %0, %1, %2, %3;" : "=l"(d) : "l"(a), "l"(b), "l"(c)); return d;
}

// ---------------- common asm helpers ----------------
__device__ __forceinline__ uint32_t smem_u32(const void* p) {
    uint32_t a;
    asm("{ .reg .u64 t; cvta.to.shared.u64 t, %1; cvt.u32.u64 %0, t; }" : "=r"(a) : "l"(p));
    return a;
}
__device__ __forceinline__ void ldsm4(uint32_t* r, uint32_t addr) {
    asm volatile("ldmatrix.sync.aligned.m8n8.x4.shared.b16 {%0,%1,%2,%3}, [%4];"
        : "=r"(r[0]), "=r"(r[1]), "=r"(r[2]), "=r"(r[3]) : "r"(addr));
}
__device__ __forceinline__ void ldsm2t(uint32_t* r, uint32_t addr) {
    asm volatile("ldmatrix.sync.aligned.m8n8.x2.trans.shared.b16 {%0,%1}, [%2];"
        : "=r"(r[0]), "=r"(r[1]) : "r"(addr));
}
__device__ __forceinline__ void mma16816(float* c, const uint32_t* a, uint32_t b0, uint32_t b1) {
    asm volatile("mma.sync.aligned.m16n8k16.row.col.f32.f16.f16.f32 "
        "{%0,%1,%2,%3}, {%4,%5,%6,%7}, {%8,%9}, {%0,%1,%2,%3};"
        : "+f"(c[0]), "+f"(c[1]), "+f"(c[2]), "+f"(c[3])
        : "r"(a[0]), "r"(a[1]), "r"(a[2]), "r"(a[3]), "r"(b0), "r"(b1));
}

// ---------------- K0: Wo fp32 -> fp16 ----------------
__global__ void k_convert_wo(const float* __restrict__ Wo) {
    int i = blockIdx.x * blockDim.x + threadIdx.x;
    float4 f = ((const float4*)Wo)[i];
    __half2* dst = (__half2*)g_woh;
    dst[2 * i]     = __floats2half2_rn(f.x, f.y);
    dst[2 * i + 1] = __floats2half2_rn(f.z, f.w);
}

// ---------------- K0b: Wq/Wk fp32 -> split hi/lo fp16 ----------------
__global__ void k_convert_w(const float* __restrict__ Wq, const float* __restrict__ Wk) {
    int i = blockIdx.x * blockDim.x + threadIdx.x;   // 4096 threads
    float q = Wq[i], k = Wk[i];
    __half qh = __float2half_rn(q);
    __half kh = __float2half_rn(k);
    g_wqh[i] = qh; g_wql[i] = __float2half_rn(q - __half2float(qh));
    g_wkh[i] = kh; g_wkl[i] = __float2half_rn(k - __half2float(kh));
}

// ---------------- K1: fused geodesic attention ----------------
// proj + mixing on HMMA (split-fp16, fp32 accum); logits/softmax exact fp32.
#define XSTR   144          // 72 halves per row (pad: conflict-free ldmatrix)
#define SM_XH  0            // x_hi [64][72]h  = 9216B each
#define SM_XL  9216
#define SM_VH  18432
#define SM_VL  27648
#define SM_WQH 36864        // weights region [4x 9216B], dead after projection
#define SM_WQL 46080
#define SM_WKH 55296
#define SM_WKL 64512
#define SM_QT  36864        // fp32 [64][68] (OVERLAYS weights; written post-barrier)
#define SM_KT  54272        // fp32 [64][68]
#define SM_ATH 73728        // attn hi: [4][16][24]h = 3072B
#define SM_ATL 76800
#define SM_SQQ 79872        // 64 floats each
#define SM_SKK 80128
#define SM_SBQ 80384
#define SM_SBK 80640
#define K1_BYTES 80896

__global__ void __launch_bounds__(256, 2) k_attn(
    const float* __restrict__ x, const float* __restrict__ v,
    const float* __restrict__ Wq_unused, const float* __restrict__ bq,
    const float* __restrict__ Wk_unused, const float* __restrict__ bk)
{
    extern __shared__ __align__(16) char sm[];
    const uint32_t sb = smem_u32(sm);
    const int t = threadIdx.x;
    const int w = t >> 5, lane = t & 31;
    const size_t b0 = (size_t)blockIdx.x * RPC;

    // ---- load x, v -> split fp16 smem tiles [64 rows][72 halves] ----
    {
        const float4* gx = (const float4*)(x + b0 * DMODEL);
        const float4* gv = (const float4*)(v + b0 * DMODEL);
#pragma unroll
        for (int i = 0; i < 4; i++) {
            const int u = t + 256 * i;            // 1024 float4 units
            const int rh = u >> 4, d4 = u & 15;
            const int off = rh * XSTR + d4 * 8;   // bytes (4 halves)
            float4 f = gx[u];
            __half2 h01 = __floats2half2_rn(f.x, f.y);
            __half2 h23 = __floats2half2_rn(f.z, f.w);
            __half2 l01 = __floats2half2_rn(f.x - __half2float(__low2half(h01)),
                                            f.y - __half2float(__high2half(h01)));
            __half2 l23 = __floats2half2_rn(f.z - __half2float(__low2half(h23)),
                                            f.w - __half2float(__high2half(h23)));
            *(__half2*)(sm + SM_XH + off)     = h01;
            *(__half2*)(sm + SM_XH + off + 4) = h23;
            *(__half2*)(sm + SM_XL + off)     = l01;
            *(__half2*)(sm + SM_XL + off + 4) = l23;
            f = gv[u];
            h01 = __floats2half2_rn(f.x, f.y);
            h23 = __floats2half2_rn(f.z, f.w);
            l01 = __floats2half2_rn(f.x - __half2float(__low2half(h01)),
                                    f.y - __half2float(__high2half(h01)));
            l23 = __floats2half2_rn(f.z - __half2float(__low2half(h23)),
                                    f.w - __half2float(__high2half(h23)));
            *(__half2*)(sm + SM_VH + off)     = h01;
            *(__half2*)(sm + SM_VH + off + 4) = h23;
            *(__half2*)(sm + SM_VL + off)     = l01;
            *(__half2*)(sm + SM_VL + off + 4) = l23;
        }
    }
    // ---- load split weights (fp16, row [e][d], stride 72h) ----
    {
        const int e = t >> 2, seg = (t & 3) * 16;       // halves
        const int doff = e * XSTR + seg * 2;
        const int goff = e * 64 + seg;
        *(uint4*)(sm + SM_WQH + doff)      = *(const uint4*)(g_wqh + goff);
        *(uint4*)(sm + SM_WQH + doff + 16) = *(const uint4*)(g_wqh + goff + 8);
        *(uint4*)(sm + SM_WQL + doff)      = *(const uint4*)(g_wql + goff);
        *(uint4*)(sm + SM_WQL + doff + 16) = *(const uint4*)(g_wql + goff + 8);
        *(uint4*)(sm + SM_WKH + doff)      = *(const uint4*)(g_wkh + goff);
        *(uint4*)(sm + SM_WKH + doff + 16) = *(const uint4*)(g_wkh + goff + 8);
        *(uint4*)(sm + SM_WKL + doff)      = *(const uint4*)(g_wkl + goff);
        *(uint4*)(sm + SM_WKL + doff + 16) = *(const uint4*)(g_wkl + goff + 8);
    }
    if (t < 64) {
        ((float*)(sm + SM_SBQ))[t] = bq[t];
        ((float*)(sm + SM_SBK))[t] = bk[t];
    }
    __syncthreads();

    // ---- projection via split-fp16 HMMA: warps 0-3 q, 4-7 k; 16 rows/warp ----
    {
        const int half = w >> 2, rows16 = (w & 3) * 16;
        const uint32_t xh = sb + SM_XH, xl = sb + SM_XL;
        const uint32_t wh = sb + (half ? SM_WKH : SM_WQH);
        const uint32_t wl = sb + (half ? SM_WKL : SM_WQL);
        const int arow = rows16 + (lane & 15);
        const uint32_t acol = (uint32_t)((lane >> 4) << 4);

        float acc[8][4];
#pragma unroll
        for (int nt = 0; nt < 8; nt++)
#pragma unroll
            for (int r = 0; r < 4; r++) acc[nt][r] = 0.f;

#pragma unroll
        for (int ks = 0; ks < 4; ks++) {
            uint32_t ah[4], al[4];
            ldsm4(ah, xh + arow * XSTR + acol + ks * 32);
            ldsm4(al, xl + arow * XSTR + acol + ks * 32);
#pragma unroll
            for (int nt2 = 0; nt2 < 4; nt2++) {
                uint32_t bh[4], bl[4];
                const uint32_t baddr = (nt2 * 16 + (lane & 15)) * XSTR + acol + ks * 32;
                ldsm4(bh, wh + baddr);
                ldsm4(bl, wl + baddr);
#pragma unroll
                for (int p = 0; p < 2; p++) {
                    const int nt = nt2 * 2 + p;
                    mma16816(acc[nt], ah, bh[p], bh[2 + p]);
                    mma16816(acc[nt], ah, bl[p], bl[2 + p]);
                    mma16816(acc[nt], al, bh[p], bh[2 + p]);
                }
            }
        }
        __syncthreads();   // all weight reads complete -> overlay region writable

        const float* bia = (const float*)(sm + (half ? SM_SBK : SM_SBQ));
        float* dst = (float*)(sm + (half ? SM_KT : SM_QT));
        float* dsq = (float*)(sm + (half ? SM_SKK : SM_SQQ));
        const int r0 = lane >> 2, cb = 2 * (lane & 3);
        float ss0 = 0.f, ss1 = 0.f;
#pragma unroll
        for (int nt = 0; nt < 8; nt++) {
            const int e0 = nt * 8;
            const float b0v = bia[e0 + cb], b1v = bia[e0 + cb + 1];
            const float c0 = acc[nt][0] + b0v, c1 = acc[nt][1] + b1v;
            const float c2 = acc[nt][2] + b0v, c3 = acc[nt][3] + b1v;
            ss0 += c0 * c0 + c1 * c1;
            ss1 += c2 * c2 + c3 * c3;
            *(float2*)&dst[(rows16 + r0) * 68 + e0 + cb]     = make_float2(c0, c1);
            *(float2*)&dst[(rows16 + r0 + 8) * 68 + e0 + cb] = make_float2(c2, c3);
        }
        ss0 += __shfl_xor_sync(0xffffffffu, ss0, 1);
        ss0 += __shfl_xor_sync(0xffffffffu, ss0, 2);
        ss1 += __shfl_xor_sync(0xffffffffu, ss1, 1);
        ss1 += __shfl_xor_sync(0xffffffffu, ss1, 2);
        if ((lane & 3) == 0) {
            dsq[rows16 + r0]     = ss0;
            dsq[rows16 + r0 + 8] = ss1;
        }
    }
    __syncthreads();

    // ---- logits + softmax (exact fp32), write split-fp16 attn ----
    {
        const float* qt  = (const float*)(sm + SM_QT);
        const float* kt  = (const float*)(sm + SM_KT);
        const float* sqq = (const float*)(sm + SM_SQQ);
        const float* skk = (const float*)(sm + SM_SKK);
        const int row = t >> 6, t64 = t & 63;
        const int h0 = (t64 >> 3) * 2, g0 = (t64 & 7) * 2;
        const float* qr0 = qt + (row * 16 + h0) * 68;
        const float* qr1 = qr0 + 68;
        const float* kr0 = kt + (row * 16 + g0) * 68;
        const float* kr1 = kr0 + 68;
        const u64t z = pack2(0.f, 0.f);
        u64t dA[2][2], dB[2][2];
#pragma unroll
        for (int i = 0; i < 2; i++)
#pragma unroll
            for (int j = 0; j < 2; j++) { dA[i][j] = z; dB[i][j] = z; }
#pragma unroll
        for (int c = 0; c < 16; c++) {
            const ulonglong2 q0 = *(const ulonglong2*)(qr0 + 4 * c);
            const ulonglong2 q1 = *(const ulonglong2*)(qr1 + 4 * c);
            const ulonglong2 k0 = *(const ulonglong2*)(kr0 + 4 * c);
            const ulonglong2 k1 = *(const ulonglong2*)(kr1 + 4 * c);
            dA[0][0] = fma2(q0.x, k0.x, dA[0][0]); dB[0][0] = fma2(q0.y, k0.y, dB[0][0]);
            dA[0][1] = fma2(q0.x, k1.x, dA[0][1]); dB[0][1] = fma2(q0.y, k1.y, dB[0][1]);
            dA[1][0] = fma2(q1.x, k0.x, dA[1][0]); dB[1][0] = fma2(q1.y, k0.y, dB[1][0]);
            dA[1][1] = fma2(q1.x, k1.x, dA[1][1]); dB[1][1] = fma2(q1.y, k1.y, dB[1][1]);
        }
        float lg[2][2];
#pragma unroll
        for (int i = 0; i < 2; i++)
#pragma unroll
            for (int j = 0; j < 2; j++) {
                float a0, a1, c0, c1;
                unpack2(dA[i][j], a0, a1);
                unpack2(dB[i][j], c0, c1);
                const float dot = (a0 + a1) + (c0 + c1);
                const float dist = fmaxf(sqq[row * 16 + h0 + i] + skk[row * 16 + g0 + j]
                                         - 2.0f * dot, 0.0f);
                lg[i][j] = -dist;
            }
#pragma unroll
        for (int i = 0; i < 2; i++) {
            float m = fmaxf(lg[i][0], lg[i][1]);
            m = fmaxf(m, __shfl_xor_sync(0xffffffffu, m, 1));
            m = fmaxf(m, __shfl_xor_sync(0xffffffffu, m, 2));
            m = fmaxf(m, __shfl_xor_sync(0xffffffffu, m, 4));
            const float e0v = __expf(lg[i][0] - m);
            const float e1v = __expf(lg[i][1] - m);
            float ssum = e0v + e1v;
            ssum += __shfl_xor_sync(0xffffffffu, ssum, 1);
            ssum += __shfl_xor_sync(0xffffffffu, ssum, 2);
            ssum += __shfl_xor_sync(0xffffffffu, ssum, 4);
            const float inv = 1.0f / ssum;
            const float a0 = e0v * inv, a1 = e1v * inv;
            const __half h0h = __float2half_rn(a0);
            const __half h1h = __float2half_rn(a1);
            const int aoff = ((row * 16 + h0 + i) * 24 + g0) * 2;   // bytes
            *(__half2*)(sm + SM_ATH + aoff) = __halves2half2(h0h, h1h);
            *(__half2*)(sm + SM_ATL + aoff) = __halves2half2(
                __float2half_rn(a0 - __half2float(h0h)),
                __float2half_rn(a1 - __half2float(h1h)));
        }
    }
    __syncthreads();

    // ---- mixing via split-fp16 HMMA: warp -> (row = w>>1, which = w&1) ----
    {
        const int row = w >> 1, which = w & 1;
        const uint32_t srch = sb + (which ? SM_VH : SM_XH);
        const uint32_t srcl = sb + (which ? SM_VL : SM_XL);
        const uint32_t ath = sb + SM_ATH + row * 768;
        const uint32_t atl = sb + SM_ATL + row * 768;
        const uint32_t aaddr = (uint32_t)((lane & 15) * 48 + ((lane >> 4) << 4));

        uint32_t ah[4], al[4];
        ldsm4(ah, ath + aaddr);
        ldsm4(al, atl + aaddr);

        float acc[8][4];
#pragma unroll
        for (int nt = 0; nt < 8; nt++)
#pragma unroll
            for (int r = 0; r < 4; r++) acc[nt][r] = 0.f;

        const uint32_t brow = (row * 16 + (lane & 15)) * XSTR;
#pragma unroll
        for (int nt = 0; nt < 8; nt++) {
            const uint32_t boff = brow + nt * 16;     // d0 = nt*8 halves
            uint32_t bh[2], bl[2];
            ldsm2t(bh, srch + boff);
            ldsm2t(bl, srcl + boff);
            mma16816(acc[nt], ah, bh[0], bh[1]);
            mma16816(acc[nt], ah, bl[0], bl[1]);
            mma16816(acc[nt], al, bh[0], bh[1]);
        }

        __half* gdst = g_mixed + ((which ? (size_t)NB : 0) + b0 + row) * DMODEL;
        const int hR = lane >> 2, dC = 2 * (lane & 3);
#pragma unroll
        for (int nt = 0; nt < 8; nt++) {
            const int d = nt * 8 + dC;
            *(__half2*)(gdst + hR * 64 + d)       = __floats2half2_rn(acc[nt][0], acc[nt][1]);
            *(__half2*)(gdst + (hR + 8) * 64 + d) = __floats2half2_rn(acc[nt][2], acc[nt][3]);
        }
    }
}

// ---------------- K2: HMMA GEMM  out[m,n] = mixed[m,:]·Wo[n,:] + bo[n] ----------
// Single-sync pipelined mainloop: prologue STAGES-1 chunks; per-iter
// wait -> sync -> prefetch (into slot finished last iter) -> compute.
#define KCH    16
#define STAGES 3
#define CHB    16384
#define STB    (2 * CHB)
#define OFF_A(s)  ((s) * STB)
#define OFF_B(s)  ((s) * STB + CHB)
#define GEMM_SMEM (STAGES * STB)     // 98304

#define SWZ(o) ((uint32_t)(o) ^ ((((uint32_t)(o)) >> 3) & 0x70u))

__device__ __forceinline__ void cp16(uint32_t dst, const void* src) {
    asm volatile("cp.async.cg.shared.global [%0], [%1], 16;" :: "r"(dst), "l"(src));
}
__device__ __forceinline__ void cp_commit() { asm volatile("cp.async.commit_group;" ::: "memory"); }
template <int N> __device__ __forceinline__ void cp_wait() {
    asm volatile("cp.async.wait_group %0;" :: "n"(N) : "memory");
}

__device__ __forceinline__ void load_chunk(uint32_t sbase, int stage, int ch,
                                           size_t m0, int n0, int t) {
#pragma unroll
    for (int i = 0; i < 8; i++) {
        const int u = t + 128 * i;
        const int r = u >> 3, c = u & 7;
        const uint32_t so = SWZ(r * 128 + c * 16);
        cp16(sbase + OFF_A(stage) + so, g_mixed + (m0 + r) * DMODEL + ch * 64 + c * 8);
        cp16(sbase + OFF_B(stage) + so, g_woh + (size_t)(n0 + r) * DMODEL + ch * 64 + c * 8);
    }
}

__global__ void __launch_bounds__(128, 2) k_gemm(const float* __restrict__ bo,
                                                 float* __restrict__ out,
                                                 int mblk0)
{
    extern __shared__ __align__(1024) char sm2[];
    const uint32_t sbase = smem_u32(sm2);
    const int t = threadIdx.x;
    const int wid = t >> 5, lane = t & 31;
    const int n0 = blockIdx.x * 128;
    const size_t m0 = (size_t)(mblk0 + blockIdx.y) * 128;
    const int wm = (wid & 1) * 64, wn = (wid >> 1) * 64;

    float acc[4][8][4];
#pragma unroll
    for (int mi = 0; mi < 4; mi++)
#pragma unroll
        for (int ni = 0; ni < 8; ni++)
#pragma unroll
            for (int r = 0; r < 4; r++) acc[mi][ni][r] = 0.f;

    // prologue: STAGES-1 chunks
#pragma unroll
    for (int c = 0; c < STAGES - 1; c++) {
        load_chunk(sbase, c, c, m0, n0, t);
        cp_commit();
    }

    const int frow = lane & 15;
    const int fcol = (lane >> 4) << 4;

    int buf = 0;
    for (int c = 0; c < KCH; c++) {
        if (c < KCH - (STAGES - 1)) cp_wait<STAGES - 2>();
        else                        cp_wait<0>();
        __syncthreads();

        // prefetch chunk c+STAGES-1 into slot (c-1+STAGES)%STAGES (freed by this barrier)
        if (c + STAGES - 1 < KCH) {
            const int ps = (c + STAGES - 1) % STAGES;
            load_chunk(sbase, ps, c + STAGES - 1, m0, n0, t);
            cp_commit();
        }

        const uint32_t abase = sbase + OFF_A(buf);
        const uint32_t bbase = sbase + OFF_B(buf);
#pragma unroll
        for (int ks = 0; ks < 4; ks++) {
            const int colb = ks * 32 + fcol;
            uint32_t a[4][4], bf[4][4];
#pragma unroll
            for (int mi = 0; mi < 4; mi++)
                ldsm4(a[mi], abase + SWZ((wm + mi * 16 + frow) * 128 + colb));
#pragma unroll
            for (int p = 0; p < 4; p++)
                ldsm4(bf[p], bbase + SWZ((wn + p * 16 + frow) * 128 + colb));
#pragma unroll
            for (int mi = 0; mi < 4; mi++)
#pragma unroll
                for (int ni = 0; ni < 8; ni++)
                    mma16816(acc[mi][ni], a[mi], bf[ni >> 1][ni & 1], bf[ni >> 1][2 + (ni & 1)]);
        }

        buf = (buf == STAGES - 1) ? 0 : buf + 1;
    }

    // epilogue: += bo, fp32 store
#pragma unroll
    for (int mi = 0; mi < 4; mi++) {
        const size_t m = m0 + wm + mi * 16 + (lane >> 2);
#pragma unroll
        for (int ni = 0; ni < 8; ni++) {
            const int n = n0 + wn + ni * 8 + (lane & 3) * 2;
            const float b0v = __ldg(bo + n), b1v = __ldg(bo + n + 1);
            float2 r0 = make_float2(acc[mi][ni][0] + b0v, acc[mi][ni][1] + b1v);
            float2 r1 = make_float2(acc[mi][ni][2] + b0v, acc[mi][ni][3] + b1v);
            *(float2*)&out[m * DMODEL + n] = r0;
            *(float2*)&out[(m + 8) * DMODEL + n] = r1;
        }
    }
}

// ---------------- launch ----------------
extern "C" void kernel_launch(void* const* d_in, const int* in_sizes, int n_in,
                              void* d_out, int out_size)
{
    const float* x  = (const float*)d_in[0];
    const float* v  = (const float*)d_in[1];
    const float* Wq = (const float*)d_in[2];
    const float* bq = (const float*)d_in[3];
    const float* Wk = (const float*)d_in[4];
    const float* bk = (const float*)d_in[5];
    const float* Wo = (const float*)d_in[6];
    const float* bo = (const float*)d_in[7];

    cudaFuncSetAttribute(k_attn, cudaFuncAttributeMaxDynamicSharedMemorySize, K1_BYTES);
    cudaFuncSetAttribute(k_gemm, cudaFuncAttributeMaxDynamicSharedMemorySize, GEMM_SMEM);

    k_convert_wo<<<DMODEL * DMODEL / 4 / 256, 256>>>(Wo);
    k_convert_w<<<HD * HD / 256, 256>>>(Wq, Wk);
    k_attn<<<NB / RPC, 256, K1_BYTES>>>(x, v, Wq, bq, Wk, bk);
    k_gemm<<<dim3(DMODEL / 128, 256), 128, GEMM_SMEM>>>(bo, (float*)d_out, 0);
    k_gemm<<<dim3(DMODEL / 128, 256), 128, GEMM_SMEM>>>(bo, (float*)d_out, 256);
}

// round 14
// speedup vs baseline: 1.1333x; 1.1333x over previous
#include <cuda_runtime.h>
#include <cuda_fp16.h>
#include <cstdint>

#define NB      32768
#define NH      16
#define HD      64
#define DMODEL  1024
#define RPC     4

typedef unsigned long long u64t;

// ---------------- scratch (device globals; no allocs allowed) ----------------
__device__ __half g_mixed[(size_t)2 * NB * DMODEL];   // [x_mixed ; v_mixed] fp16
__device__ __half g_woh[DMODEL * DMODEL];             // Wo fp16
__device__ __half g_wqh[HD * HD], g_wql[HD * HD];     // Wq split hi/lo fp16
__device__ __half g_wkh[HD * HD], g_wkl[HD * HD];     // Wk split hi/lo fp16

// ---------------- common asm helpers ----------------
__device__ __forceinline__ uint32_t smem_u32(const void* p) {
    uint32_t a;
    asm("{ .reg .u64 t; cvta.to.shared.u64 t, %1; cvt.u32.u64 %0, t; }" : "=r"(a) : "l"(p));
    return a;
}
__device__ __forceinline__ void ldsm4(uint32_t* r, uint32_t addr) {
    asm volatile("ldmatrix.sync.aligned.m8n8.x4.shared.b16 {%0,%1,%2,%3}, [%4];"
        : "=r"(r[0]), "=r"(r[1]), "=r"(r[2]), "=r"(r[3]) : "r"(addr));
}
__device__ __forceinline__ void ldsm2t(uint32_t* r, uint32_t addr) {
    asm volatile("ldmatrix.sync.aligned.m8n8.x2.trans.shared.b16 {%0,%1}, [%2];"
        : "=r"(r[0]), "=r"(r[1]) : "r"(addr));
}
__device__ __forceinline__ void mma16816(float* c, const uint32_t* a, uint32_t b0, uint32_t b1) {
    asm volatile("mma.sync.aligned.m16n8k16.row.col.f32.f16.f16.f32 "
        "{%0,%1,%2,%3}, {%4,%5,%6,%7}, {%8,%9}, {%0,%1,%2,%3};"
        : "+f"(c[0]), "+f"(c[1]), "+f"(c[2]), "+f"(c[3])
        : "r"(a[0]), "r"(a[1]), "r"(a[2]), "r"(a[3]), "r"(b0), "r"(b1));
}

// ---------------- K0: Wo fp32 -> fp16 ----------------
__global__ void k_convert_wo(const float* __restrict__ Wo) {
    int i = blockIdx.x * blockDim.x + threadIdx.x;
    float4 f = ((const float4*)Wo)[i];
    __half2* dst = (__half2*)g_woh;
    dst[2 * i]     = __floats2half2_rn(f.x, f.y);
    dst[2 * i + 1] = __floats2half2_rn(f.z, f.w);
}

// ---------------- K0b: Wq/Wk fp32 -> split hi/lo fp16 ----------------
__global__ void k_convert_w(const float* __restrict__ Wq, const float* __restrict__ Wk) {
    int i = blockIdx.x * blockDim.x + threadIdx.x;   // 4096 threads
    float q = Wq[i], k = Wk[i];
    __half qh = __float2half_rn(q);
    __half kh = __float2half_rn(k);
    g_wqh[i] = qh; g_wql[i] = __float2half_rn(q - __half2float(qh));
    g_wkh[i] = kh; g_wkl[i] = __float2half_rn(k - __half2float(kh));
}

// ---------------- K1: fused geodesic attention ----------------
// proj + logits + mixing all on HMMA (split-fp16, fp32 accum); softmax exact fp32.
#define XSTR   144          // 72 halves per row (pad: conflict-free ldmatrix)
#define SM_XH  0            // x_hi [64][72]h  = 9216B each
#define SM_XL  9216
#define SM_VH  18432
#define SM_VL  27648
#define SM_WQH 36864        // weights region [4x 9216B], dead after projection
#define SM_WQL 46080
#define SM_WKH 55296
#define SM_WKL 64512
#define SM_QH  36864        // split q/k tiles [64][72]h (OVERLAY weights, post-barrier)
#define SM_QL  46080
#define SM_KH  55296
#define SM_KL  64512
#define SM_ATH 73728        // attn hi: [4][16][24]h = 3072B
#define SM_ATL 76800
#define SM_SQQ 79872        // 64 floats each
#define SM_SKK 80128
#define SM_SBQ 80384
#define SM_SBK 80640
#define K1_BYTES 80896

__global__ void __launch_bounds__(256, 2) k_attn(
    const float* __restrict__ x, const float* __restrict__ v,
    const float* __restrict__ Wq_unused, const float* __restrict__ bq,
    const float* __restrict__ Wk_unused, const float* __restrict__ bk)
{
    extern __shared__ __align__(16) char sm[];
    const uint32_t sb = smem_u32(sm);
    const int t = threadIdx.x;
    const int w = t >> 5, lane = t & 31;
    const size_t b0 = (size_t)blockIdx.x * RPC;

    // ---- load x, v -> split fp16 smem tiles [64 rows][72 halves] ----
    {
        const float4* gx = (const float4*)(x + b0 * DMODEL);
        const float4* gv = (const float4*)(v + b0 * DMODEL);
#pragma unroll
        for (int i = 0; i < 4; i++) {
            const int u = t + 256 * i;            // 1024 float4 units
            const int rh = u >> 4, d4 = u & 15;
            const int off = rh * XSTR + d4 * 8;   // bytes (4 halves)
            float4 f = gx[u];
            __half2 h01 = __floats2half2_rn(f.x, f.y);
            __half2 h23 = __floats2half2_rn(f.z, f.w);
            __half2 l01 = __floats2half2_rn(f.x - __half2float(__low2half(h01)),
                                            f.y - __half2float(__high2half(h01)));
            __half2 l23 = __floats2half2_rn(f.z - __half2float(__low2half(h23)),
                                            f.w - __half2float(__high2half(h23)));
            *(__half2*)(sm + SM_XH + off)     = h01;
            *(__half2*)(sm + SM_XH + off + 4) = h23;
            *(__half2*)(sm + SM_XL + off)     = l01;
            *(__half2*)(sm + SM_XL + off + 4) = l23;
            f = gv[u];
            h01 = __floats2half2_rn(f.x, f.y);
            h23 = __floats2half2_rn(f.z, f.w);
            l01 = __floats2half2_rn(f.x - __half2float(__low2half(h01)),
                                    f.y - __half2float(__high2half(h01)));
            l23 = __floats2half2_rn(f.z - __half2float(__low2half(h23)),
                                    f.w - __half2float(__high2half(h23)));
            *(__half2*)(sm + SM_VH + off)     = h01;
            *(__half2*)(sm + SM_VH + off + 4) = h23;
            *(__half2*)(sm + SM_VL + off)     = l01;
            *(__half2*)(sm + SM_VL + off + 4) = l23;
        }
    }
    // ---- load split weights (fp16, row [e][d], stride 72h) ----
    {
        const int e = t >> 2, seg = (t & 3) * 16;       // halves
        const int doff = e * XSTR + seg * 2;
        const int goff = e * 64 + seg;
        *(uint4*)(sm + SM_WQH + doff)      = *(const uint4*)(g_wqh + goff);
        *(uint4*)(sm + SM_WQH + doff + 16) = *(const uint4*)(g_wqh + goff + 8);
        *(uint4*)(sm + SM_WQL + doff)      = *(const uint4*)(g_wql + goff);
        *(uint4*)(sm + SM_WQL + doff + 16) = *(const uint4*)(g_wql + goff + 8);
        *(uint4*)(sm + SM_WKH + doff)      = *(const uint4*)(g_wkh + goff);
        *(uint4*)(sm + SM_WKH + doff + 16) = *(const uint4*)(g_wkh + goff + 8);
        *(uint4*)(sm + SM_WKL + doff)      = *(const uint4*)(g_wkl + goff);
        *(uint4*)(sm + SM_WKL + doff + 16) = *(const uint4*)(g_wkl + goff + 8);
    }
    if (t < 64) {
        ((float*)(sm + SM_SBQ))[t] = bq[t];
        ((float*)(sm + SM_SBK))[t] = bk[t];
    }
    __syncthreads();

    // ---- projection via split-fp16 HMMA: warps 0-3 q, 4-7 k; 16 rows/warp ----
    {
        const int half = w >> 2, rows16 = (w & 3) * 16;
        const uint32_t xh = sb + SM_XH, xl = sb + SM_XL;
        const uint32_t wh = sb + (half ? SM_WKH : SM_WQH);
        const uint32_t wl = sb + (half ? SM_WKL : SM_WQL);
        const int arow = rows16 + (lane & 15);
        const uint32_t acol = (uint32_t)((lane >> 4) << 4);

        float acc[8][4];
#pragma unroll
        for (int nt = 0; nt < 8; nt++)
#pragma unroll
            for (int r = 0; r < 4; r++) acc[nt][r] = 0.f;

#pragma unroll
        for (int ks = 0; ks < 4; ks++) {
            uint32_t ah[4], al[4];
            ldsm4(ah, xh + arow * XSTR + acol + ks * 32);
            ldsm4(al, xl + arow * XSTR + acol + ks * 32);
#pragma unroll
            for (int nt2 = 0; nt2 < 4; nt2++) {
                uint32_t bh[4], bl[4];
                const uint32_t baddr = (nt2 * 16 + (lane & 15)) * XSTR + acol + ks * 32;
                ldsm4(bh, wh + baddr);
                ldsm4(bl, wl + baddr);
#pragma unroll
                for (int p = 0; p < 2; p++) {
                    const int nt = nt2 * 2 + p;
                    mma16816(acc[nt], ah, bh[p], bh[2 + p]);
                    mma16816(acc[nt], ah, bl[p], bl[2 + p]);
                    mma16816(acc[nt], al, bh[p], bh[2 + p]);
                }
            }
        }
        __syncthreads();   // all weight reads complete -> overlay region writable

        const float* bia = (const float*)(sm + (half ? SM_SBK : SM_SBQ));
        char* dhi = sm + (half ? SM_KH : SM_QH);
        char* dlo = sm + (half ? SM_KL : SM_QL);
        float* dsq = (float*)(sm + (half ? SM_SKK : SM_SQQ));
        const int r0 = lane >> 2, cb = 2 * (lane & 3);
        float ss0 = 0.f, ss1 = 0.f;
#pragma unroll
        for (int nt = 0; nt < 8; nt++) {
            const int e0 = nt * 8;
            const float b0v = bia[e0 + cb], b1v = bia[e0 + cb + 1];
            const float c0 = acc[nt][0] + b0v, c1 = acc[nt][1] + b1v;
            const float c2 = acc[nt][2] + b0v, c3 = acc[nt][3] + b1v;
            ss0 += c0 * c0 + c1 * c1;
            ss1 += c2 * c2 + c3 * c3;
            // split fp16 store: rows rows16+r0 and +8, cols e0+cb..+1 (stride 72h)
            const int offA = (rows16 + r0) * XSTR + (e0 + cb) * 2;
            const int offB = (rows16 + r0 + 8) * XSTR + (e0 + cb) * 2;
            __half2 h01 = __floats2half2_rn(c0, c1);
            __half2 h23 = __floats2half2_rn(c2, c3);
            *(__half2*)(dhi + offA) = h01;
            *(__half2*)(dhi + offB) = h23;
            *(__half2*)(dlo + offA) = __floats2half2_rn(
                c0 - __half2float(__low2half(h01)), c1 - __half2float(__high2half(h01)));
            *(__half2*)(dlo + offB) = __floats2half2_rn(
                c2 - __half2float(__low2half(h23)), c3 - __half2float(__high2half(h23)));
        }
        ss0 += __shfl_xor_sync(0xffffffffu, ss0, 1);
        ss0 += __shfl_xor_sync(0xffffffffu, ss0, 2);
        ss1 += __shfl_xor_sync(0xffffffffu, ss1, 1);
        ss1 += __shfl_xor_sync(0xffffffffu, ss1, 2);
        if ((lane & 3) == 0) {
            dsq[rows16 + r0]     = ss0;
            dsq[rows16 + r0 + 8] = ss1;
        }
    }
    __syncthreads();

    // ---- logits via split-fp16 HMMA + in-register softmax: warps 0-3 (row = w) ----
    if (w < 4) {
        const int row = w, r16 = row * 16;
        const uint32_t qh = sb + SM_QH, ql = sb + SM_QL;
        const uint32_t kh = sb + SM_KH, kl = sb + SM_KL;
        const int arow = r16 + (lane & 15);
        const uint32_t acol = (uint32_t)((lane >> 4) << 4);

        float dacc[2][4];
#pragma unroll
        for (int tt = 0; tt < 2; tt++)
#pragma unroll
            for (int r = 0; r < 4; r++) dacc[tt][r] = 0.f;

#pragma unroll
        for (int ks = 0; ks < 4; ks++) {
            const uint32_t off = arow * XSTR + acol + ks * 32;
            uint32_t ah[4], al[4], bh[4], bl[4];
            ldsm4(ah, qh + off);
            ldsm4(al, ql + off);
            ldsm4(bh, kh + off);
            ldsm4(bl, kl + off);
#pragma unroll
            for (int tt = 0; tt < 2; tt++) {
                mma16816(dacc[tt], ah, bh[tt], bh[2 + tt]);
                mma16816(dacc[tt], ah, bl[tt], bl[2 + tt]);
                mma16816(dacc[tt], al, bh[tt], bh[2 + tt]);
            }
        }

        const float* sqq = (const float*)(sm + SM_SQQ);
        const float* skk = (const float*)(sm + SM_SKK);
        const int hA = lane >> 2;            // rows hA and hA+8
        const int gB = 2 * (lane & 3);
        const float qsA = sqq[r16 + hA], qsB = sqq[r16 + hA + 8];

        float lg[2][4];
#pragma unroll
        for (int tt = 0; tt < 2; tt++) {
            const float k0 = skk[r16 + tt * 8 + gB];
            const float k1 = skk[r16 + tt * 8 + gB + 1];
            lg[tt][0] = -fmaxf(qsA + k0 - 2.0f * dacc[tt][0], 0.f);
            lg[tt][1] = -fmaxf(qsA + k1 - 2.0f * dacc[tt][1], 0.f);
            lg[tt][2] = -fmaxf(qsB + k0 - 2.0f * dacc[tt][2], 0.f);
            lg[tt][3] = -fmaxf(qsB + k1 - 2.0f * dacc[tt][3], 0.f);
        }
        // row softmax: rows hA (j=0,1) and hA+8 (j=2,3); 16 cols spread over
        // 4 lanes (lane&3 group) x 2 cols x 2 n-tiles.
        float mA = fmaxf(fmaxf(lg[0][0], lg[0][1]), fmaxf(lg[1][0], lg[1][1]));
        float mB = fmaxf(fmaxf(lg[0][2], lg[0][3]), fmaxf(lg[1][2], lg[1][3]));
        mA = fmaxf(mA, __shfl_xor_sync(0xffffffffu, mA, 1));
        mA = fmaxf(mA, __shfl_xor_sync(0xffffffffu, mA, 2));
        mB = fmaxf(mB, __shfl_xor_sync(0xffffffffu, mB, 1));
        mB = fmaxf(mB, __shfl_xor_sync(0xffffffffu, mB, 2));
        float ev[2][4];
        ev[0][0] = __expf(lg[0][0] - mA); ev[0][1] = __expf(lg[0][1] - mA);
        ev[1][0] = __expf(lg[1][0] - mA); ev[1][1] = __expf(lg[1][1] - mA);
        ev[0][2] = __expf(lg[0][2] - mB); ev[0][3] = __expf(lg[0][3] - mB);
        ev[1][2] = __expf(lg[1][2] - mB); ev[1][3] = __expf(lg[1][3] - mB);
        float sA = ev[0][0] + ev[0][1] + ev[1][0] + ev[1][1];
        float sB = ev[0][2] + ev[0][3] + ev[1][2] + ev[1][3];
        sA += __shfl_xor_sync(0xffffffffu, sA, 1);
        sA += __shfl_xor_sync(0xffffffffu, sA, 2);
        sB += __shfl_xor_sync(0xffffffffu, sB, 1);
        sB += __shfl_xor_sync(0xffffffffu, sB, 2);
        const float iA = 1.0f / sA, iB = 1.0f / sB;

        // write split-fp16 attn to ATH/ATL (layout identical to before)
#pragma unroll
        for (int tt = 0; tt < 2; tt++) {
            const float a0 = ev[tt][0] * iA, a1 = ev[tt][1] * iA;
            const float a2 = ev[tt][2] * iB, a3 = ev[tt][3] * iB;
            const int g0 = tt * 8 + gB;
            const int offA = ((r16 + hA) * 24 + g0) * 2;
            const int offB = ((r16 + hA + 8) * 24 + g0) * 2;
            __half2 h01 = __floats2half2_rn(a0, a1);
            __half2 h23 = __floats2half2_rn(a2, a3);
            *(__half2*)(sm + SM_ATH + offA) = h01;
            *(__half2*)(sm + SM_ATH + offB) = h23;
            *(__half2*)(sm + SM_ATL + offA) = __floats2half2_rn(
                a0 - __half2float(__low2half(h01)), a1 - __half2float(__high2half(h01)));
            *(__half2*)(sm + SM_ATL + offB) = __floats2half2_rn(
                a2 - __half2float(__low2half(h23)), a3 - __half2float(__high2half(h23)));
        }
    }
    __syncthreads();

    // ---- mixing via split-fp16 HMMA: warp -> (row = w>>1, which = w&1) ----
    {
        const int row = w >> 1, which = w & 1;
        const uint32_t srch = sb + (which ? SM_VH : SM_XH);
        const uint32_t srcl = sb + (which ? SM_VL : SM_XL);
        const uint32_t ath = sb + SM_ATH + row * 768;
        const uint32_t atl = sb + SM_ATL + row * 768;
        const uint32_t aaddr = (uint32_t)((lane & 15) * 48 + ((lane >> 4) << 4));

        uint32_t ah[4], al[4];
        ldsm4(ah, ath + aaddr);
        ldsm4(al, atl + aaddr);

        float acc[8][4];
#pragma unroll
        for (int nt = 0; nt < 8; nt++)
#pragma unroll
            for (int r = 0; r < 4; r++) acc[nt][r] = 0.f;

        const uint32_t brow = (row * 16 + (lane & 15)) * XSTR;
#pragma unroll
        for (int nt = 0; nt < 8; nt++) {
            const uint32_t boff = brow + nt * 16;     // d0 = nt*8 halves
            uint32_t bh[2], bl[2];
            ldsm2t(bh, srch + boff);
            ldsm2t(bl, srcl + boff);
            mma16816(acc[nt], ah, bh[0], bh[1]);
            mma16816(acc[nt], ah, bl[0], bl[1]);
            mma16816(acc[nt], al, bh[0], bh[1]);
        }

        __half* gdst = g_mixed + ((which ? (size_t)NB : 0) + b0 + row) * DMODEL;
        const int hR = lane >> 2, dC = 2 * (lane & 3);
#pragma unroll
        for (int nt = 0; nt < 8; nt++) {
            const int d = nt * 8 + dC;
            *(__half2*)(gdst + hR * 64 + d)       = __floats2half2_rn(acc[nt][0], acc[nt][1]);
            *(__half2*)(gdst + (hR + 8) * 64 + d) = __floats2half2_rn(acc[nt][2], acc[nt][3]);
        }
    }
}

// ---------------- K2: HMMA GEMM  out[m,n] = mixed[m,:]·Wo[n,:] + bo[n] ----------
// (R11 mainloop — at the measured mma.sync ceiling; do not touch)
#define KCH    16
#define STAGES 3
#define CHB    16384
#define STB    (2 * CHB)
#define OFF_A(s)  ((s) * STB)
#define OFF_B(s)  ((s) * STB + CHB)
#define GEMM_SMEM (STAGES * STB)     // 98304

#define SWZ(o) ((uint32_t)(o) ^ ((((uint32_t)(o)) >> 3) & 0x70u))

__device__ __forceinline__ void cp16(uint32_t dst, const void* src) {
    asm volatile("cp.async.cg.shared.global [%0], [%1], 16;" :: "r"(dst), "l"(src));
}
__device__ __forceinline__ void cp_commit() { asm volatile("cp.async.commit_group;" ::: "memory"); }
template <int N> __device__ __forceinline__ void cp_wait() {
    asm volatile("cp.async.wait_group %0;" :: "n"(N) : "memory");
}

__device__ __forceinline__ void load_chunk(uint32_t sbase, int stage, int ch,
                                           size_t m0, int n0, int t) {
#pragma unroll
    for (int i = 0; i < 8; i++) {
        const int u = t + 128 * i;
        const int r = u >> 3, c = u & 7;
        const uint32_t so = SWZ(r * 128 + c * 16);
        cp16(sbase + OFF_A(stage) + so, g_mixed + (m0 + r) * DMODEL + ch * 64 + c * 8);
        cp16(sbase + OFF_B(stage) + so, g_woh + (size_t)(n0 + r) * DMODEL + ch * 64 + c * 8);
    }
}

__global__ void __launch_bounds__(128, 2) k_gemm(const float* __restrict__ bo,
                                                 float* __restrict__ out,
                                                 int mblk0)
{
    extern __shared__ __align__(1024) char sm2[];
    const uint32_t sbase = smem_u32(sm2);
    const int t = threadIdx.x;
    const int wid = t >> 5, lane = t & 31;
    const int n0 = blockIdx.x * 128;
    const size_t m0 = (size_t)(mblk0 + blockIdx.y) * 128;
    const int wm = (wid & 1) * 64, wn = (wid >> 1) * 64;

    float acc[4][8][4];
#pragma unroll
    for (int mi = 0; mi < 4; mi++)
#pragma unroll
        for (int ni = 0; ni < 8; ni++)
#pragma unroll
            for (int r = 0; r < 4; r++) acc[mi][ni][r] = 0.f;

#pragma unroll
    for (int c = 0; c < STAGES; c++) {
        load_chunk(sbase, c, c, m0, n0, t);
        cp_commit();
    }

    const int frow = lane & 15;
    const int fcol = (lane >> 4) << 4;

    int buf = 0;
    for (int c = 0; c < KCH; c++) {
        cp_wait<STAGES - 1>();
        __syncthreads();

        const uint32_t abase = sbase + OFF_A(buf);
        const uint32_t bbase = sbase + OFF_B(buf);
#pragma unroll
        for (int ks = 0; ks < 4; ks++) {
            const int colb = ks * 32 + fcol;
            uint32_t a[4][4], bf[4][4];
#pragma unroll
            for (int mi = 0; mi < 4; mi++)
                ldsm4(a[mi], abase + SWZ((wm + mi * 16 + frow) * 128 + colb));
#pragma unroll
            for (int p = 0; p < 4; p++)
                ldsm4(bf[p], bbase + SWZ((wn + p * 16 + frow) * 128 + colb));
#pragma unroll
            for (int mi = 0; mi < 4; mi++)
#pragma unroll
                for (int ni = 0; ni < 8; ni++)
                    mma16816(acc[mi][ni], a[mi], bf[ni >> 1][ni & 1], bf[ni >> 1][2 + (ni & 1)]);
        }
        __syncthreads();

        if (c + STAGES < KCH)
            load_chunk(sbase, buf, c + STAGES, m0, n0, t);
        cp_commit();

        buf = (buf == STAGES - 1) ? 0 : buf + 1;
    }

#pragma unroll
    for (int mi = 0; mi < 4; mi++) {
        const size_t m = m0 + wm + mi * 16 + (lane >> 2);
#pragma unroll
        for (int ni = 0; ni < 8; ni++) {
            const int n = n0 + wn + ni * 8 + (lane & 3) * 2;
            const float b0v = __ldg(bo + n), b1v = __ldg(bo + n + 1);
            float2 r0 = make_float2(acc[mi][ni][0] + b0v, acc[mi][ni][1] + b1v);
            float2 r1 = make_float2(acc[mi][ni][2] + b0v, acc[mi][ni][3] + b1v);
            *(float2*)&out[m * DMODEL + n] = r0;
            *(float2*)&out[(m + 8) * DMODEL + n] = r1;
        }
    }
}

// ---------------- launch ----------------
extern "C" void kernel_launch(void* const* d_in, const int* in_sizes, int n_in,
                              void* d_out, int out_size)
{
    const float* x  = (const float*)d_in[0];
    const float* v  = (const float*)d_in[1];
    const float* Wq = (const float*)d_in[2];
    const float* bq = (const float*)d_in[3];
    const float* Wk = (const float*)d_in[4];
    const float* bk = (const float*)d_in[5];
    const float* Wo = (const float*)d_in[6];
    const float* bo = (const float*)d_in[7];

    cudaFuncSetAttribute(k_attn, cudaFuncAttributeMaxDynamicSharedMemorySize, K1_BYTES);
    cudaFuncSetAttribute(k_gemm, cudaFuncAttributeMaxDynamicSharedMemorySize, GEMM_SMEM);

    k_convert_wo<<<DMODEL * DMODEL / 4 / 256, 256>>>(Wo);
    k_convert_w<<<HD * HD / 256, 256>>>(Wq, Wk);
    k_attn<<<NB / RPC, 256, K1_BYTES>>>(x, v, Wq, bq, Wk, bk);
    k_gemm<<<dim3(DMODEL / 128, 256), 128, GEMM_SMEM>>>(bo, (float*)d_out, 0);
    k_gemm<<<dim3(DMODEL / 128, 256), 128, GEMM_SMEM>>>(bo, (float*)d_out, 256);
}